// round 1
// baseline (speedup 1.0000x reference)
#include <cuda_runtime.h>
#include <math.h>

// ---------------------------------------------------------------------------
// RadiomicsPreservationLoss — fused single-pass stencil + reduction
// inputs (metadata order): input_img, output_img, roi_mask  [32,1,512,512] f32
// output: [intensity, texture, shape, total]  (4 x f32)
// ---------------------------------------------------------------------------

#define HH 512
#define WW 512
#define BB 32
#define STRIP 32
#define STRIPS (HH / STRIP)        // 16
#define NBLK (BB * STRIPS)         // 512
#define NTHR 256
#define SSTR 516                   // row stride in smem (514 used + pad, 16B-aligned)

__device__ double g_acc[11];       // 0:Σm 1..4:inp M1..M4 5..8:out M1..M4 9:tex 10:shape

__global__ void k_zero() {
    if (threadIdx.x < 11) g_acc[threadIdx.x] = 0.0;
}

__device__ __forceinline__ void load_rows(
    float (*sA)[SSTR], float (*sB)[SSTR],
    const float* __restrict__ bi, const float* __restrict__ bo,
    int rA, int rB, int ty, int c0)
{
    int r = ty ? rB : rA;
    int slot = r & 3;
    float4 vi = make_float4(0.f, 0.f, 0.f, 0.f);
    float4 vo = vi;
    if ((unsigned)r < (unsigned)HH) {
        vi = *(const float4*)(bi + r * WW + c0);
        vo = *(const float4*)(bo + r * WW + c0);
    }
    float* pa = &sA[slot][c0 + 1];
    pa[0] = vi.x; pa[1] = vi.y; pa[2] = vi.z; pa[3] = vi.w;
    float* pb = &sB[slot][c0 + 1];
    pb[0] = vo.x; pb[1] = vo.y; pb[2] = vo.z; pb[3] = vo.w;
}

__global__ void __launch_bounds__(NTHR) k_main(
    const float* __restrict__ g_in,
    const float* __restrict__ g_out,
    const float* __restrict__ g_mask)
{
    __shared__ float sA[4][SSTR];   // input rows ring buffer
    __shared__ float sB[4][SSTR];   // output rows ring buffer
    __shared__ float sred[11][8];

    const int t  = threadIdx.x;
    const int tx = t & 127;
    const int ty = t >> 7;
    const int c0 = tx << 2;

    const int batch = blockIdx.x / STRIPS;
    const int strip = blockIdx.x % STRIPS;
    const int R0    = strip * STRIP;
    const float* bi = g_in   + (size_t)batch * HH * WW;
    const float* bo = g_out  + (size_t)batch * HH * WW;
    const float* bm = g_mask + (size_t)batch * HH * WW;

    // zero the halo columns once (loads never touch idx 0 / 513)
    if (t < 4) {
        sA[t][0] = 0.f; sA[t][513] = 0.f;
        sB[t][0] = 0.f; sB[t][513] = 0.f;
    }

    // preload rows R0-1 .. R0+2 into slots (row & 3)
    load_rows(sA, sB, bi, bo, R0 - 1, R0,     ty, c0);
    load_rows(sA, sB, bi, bo, R0 + 1, R0 + 2, ty, c0);
    __syncthreads();

    float msum = 0.f;
    float xi1 = 0.f, xi2 = 0.f, xi3 = 0.f, xi4 = 0.f;
    float yo1 = 0.f, yo2 = 0.f, yo3 = 0.f, yo4 = 0.f;
    float texs = 0.f, shps = 0.f;
    const float inv9 = 1.f / 9.f;

    for (int i = 0; i < STRIP; i += 2) {
        const int rr  = R0 + i + ty;
        const int sm1 = (rr - 1) & 3;
        const int s0  =  rr      & 3;
        const int sp1 = (rr + 1) & 3;

        float a0[6], a1[6], a2[6];
        float4 q;
        // ---- input neighborhood ----
        q = *(const float4*)&sA[sm1][c0];
        a0[0] = q.x; a0[1] = q.y; a0[2] = q.z; a0[3] = q.w;
        a0[4] = sA[sm1][c0 + 4]; a0[5] = sA[sm1][c0 + 5];
        q = *(const float4*)&sA[s0][c0];
        a1[0] = q.x; a1[1] = q.y; a1[2] = q.z; a1[3] = q.w;
        a1[4] = sA[s0][c0 + 4]; a1[5] = sA[s0][c0 + 5];
        q = *(const float4*)&sA[sp1][c0];
        a2[0] = q.x; a2[1] = q.y; a2[2] = q.z; a2[3] = q.w;
        a2[4] = sA[sp1][c0 + 4]; a2[5] = sA[sp1][c0 + 5];

        float cs[6], cq[6];
        #pragma unroll
        for (int j = 0; j < 6; j++) {
            cs[j] = a0[j] + a1[j] + a2[j];
            float u = a0[j] * a0[j];
            u = fmaf(a1[j], a1[j], u);
            cq[j] = fmaf(a2[j], a2[j], u);
        }
        float var_i[4], lap_i[4], xc[4];
        #pragma unroll
        for (int p = 0; p < 4; p++) {
            float S = cs[p] + cs[p + 1] + cs[p + 2];
            float Q = cq[p] + cq[p + 1] + cq[p + 2];
            float bmn = S * inv9;
            var_i[p] = fmaf(-bmn, bmn, Q * inv9);
            lap_i[p] = fmaf(-5.f, a1[p + 1], cs[p + 1] + a1[p] + a1[p + 2]);
            xc[p] = a1[p + 1];
        }

        // ---- output neighborhood (reuse regs) ----
        q = *(const float4*)&sB[sm1][c0];
        a0[0] = q.x; a0[1] = q.y; a0[2] = q.z; a0[3] = q.w;
        a0[4] = sB[sm1][c0 + 4]; a0[5] = sB[sm1][c0 + 5];
        q = *(const float4*)&sB[s0][c0];
        a1[0] = q.x; a1[1] = q.y; a1[2] = q.z; a1[3] = q.w;
        a1[4] = sB[s0][c0 + 4]; a1[5] = sB[s0][c0 + 5];
        q = *(const float4*)&sB[sp1][c0];
        a2[0] = q.x; a2[1] = q.y; a2[2] = q.z; a2[3] = q.w;
        a2[4] = sB[sp1][c0 + 4]; a2[5] = sB[sp1][c0 + 5];

        #pragma unroll
        for (int j = 0; j < 6; j++) {
            cs[j] = a0[j] + a1[j] + a2[j];
            float u = a0[j] * a0[j];
            u = fmaf(a1[j], a1[j], u);
            cq[j] = fmaf(a2[j], a2[j], u);
        }
        float var_o[4], lap_o[4], yc[4];
        #pragma unroll
        for (int p = 0; p < 4; p++) {
            float S = cs[p] + cs[p + 1] + cs[p + 2];
            float Q = cq[p] + cq[p + 1] + cq[p + 2];
            float bmn = S * inv9;
            var_o[p] = fmaf(-bmn, bmn, Q * inv9);
            lap_o[p] = fmaf(-5.f, a1[p + 1], cs[p + 1] + a1[p] + a1[p + 2]);
            yc[p] = a1[p + 1];
        }

        // ---- mask + accumulate ----
        float4 mv = *(const float4*)(bm + rr * WW + c0);
        float mvv[4] = { mv.x, mv.y, mv.z, mv.w };
        #pragma unroll
        for (int p = 0; p < 4; p++) {
            float m = mvv[p];
            msum += m;
            float x = xc[p], y = yc[p];
            float x2 = x * x, y2 = y * y;
            float qx = x2 * m, qy = y2 * m;
            xi1 = fmaf(x, m, xi1);  xi2 += qx;
            xi3 = fmaf(x, qx, xi3); xi4 = fmaf(x2, qx, xi4);
            yo1 = fmaf(y, m, yo1);  yo2 += qy;
            yo3 = fmaf(y, qy, yo3); yo4 = fmaf(y2, qy, yo4);
            texs = fmaf(fabsf(var_o[p] - var_i[p]), m, texs);
            shps = fmaf(fabsf(lap_o[p] - lap_i[p]), m, shps);
        }

        __syncthreads();                 // all reads of slots complete
        if (i + 2 < STRIP) {
            load_rows(sA, sB, bi, bo, R0 + i + 3, R0 + i + 4, ty, c0);
        }
        __syncthreads();                 // new rows visible
    }

    // ---- block reduction: warp shuffle -> smem -> fp64 atomics ----
    float acc[11] = { msum, xi1, xi2, xi3, xi4, yo1, yo2, yo3, yo4, texs, shps };
    #pragma unroll
    for (int k = 0; k < 11; k++) {
        float v = acc[k];
        #pragma unroll
        for (int off = 16; off; off >>= 1)
            v += __shfl_xor_sync(0xffffffffu, v, off);
        if ((t & 31) == 0) sred[k][t >> 5] = v;
    }
    __syncthreads();
    if (t < 11) {
        double s = 0.0;
        #pragma unroll
        for (int w = 0; w < 8; w++) s += (double)sred[t][w];
        atomicAdd(&g_acc[t], s);
    }
}

__global__ void k_final(float* __restrict__ out) {
    const double EPS = 1e-8;
    const double NTOT = (double)BB * HH * WW;

    double M0 = g_acc[0];
    double ms = M0 + EPS;

    double Mi1 = g_acc[1], Mi2 = g_acc[2], Mi3 = g_acc[3], Mi4 = g_acc[4];
    double Mo1 = g_acc[5], Mo2 = g_acc[6], Mo3 = g_acc[7], Mo4 = g_acc[8];

    double im = Mi1 / ms, om = Mo1 / ms;
    double im2 = im * im, om2 = om * om;

    double c2i = Mi2 - 2.0 * im * Mi1 + im2 * M0;
    double c3i = Mi3 - 3.0 * im * Mi2 + 3.0 * im2 * Mi1 - im2 * im * M0;
    double c4i = Mi4 - 4.0 * im * Mi3 + 6.0 * im2 * Mi2 - 4.0 * im2 * im * Mi1 + im2 * im2 * M0;

    double c2o = Mo2 - 2.0 * om * Mo1 + om2 * M0;
    double c3o = Mo3 - 3.0 * om * Mo2 + 3.0 * om2 * Mo1 - om2 * om * M0;
    double c4o = Mo4 - 4.0 * om * Mo3 + 6.0 * om2 * Mo2 - 4.0 * om2 * om * Mo1 + om2 * om2 * M0;

    double iv = c2i / ms, ov = c2o / ms;
    double isk = c3i / (ms * (iv * sqrt(iv) + EPS));
    double osk = c3o / (ms * (ov * sqrt(ov) + EPS));
    double iku = c4i / (ms * (iv * iv + EPS));
    double oku = c4o / (ms * (ov * ov + EPS));

    double dm = im - om, dv = iv - ov, dsk = isk - osk, dku = iku - oku;
    double inten = dm * dm + dv * dv + dsk * dsk + dku * dku;
    double tex = g_acc[9]  / NTOT;
    double shp = g_acc[10] / NTOT;
    double total = 1.0 * inten + 1.0 * tex + 0.5 * shp;

    out[0] = (float)inten;
    out[1] = (float)tex;
    out[2] = (float)shp;
    out[3] = (float)total;
}

extern "C" void kernel_launch(void* const* d_in, const int* in_sizes, int n_in,
                              void* d_out, int out_size) {
    const float* in_img  = (const float*)d_in[0];
    const float* out_img = (const float*)d_in[1];
    const float* mask    = (const float*)d_in[2];

    k_zero<<<1, 32>>>();
    k_main<<<NBLK, NTHR>>>(in_img, out_img, mask);
    k_final<<<1, 1>>>((float*)d_out);
}

// round 2
// speedup vs baseline: 1.5663x; 1.5663x over previous
#include <cuda_runtime.h>
#include <math.h>

// ---------------------------------------------------------------------------
// RadiomicsPreservationLoss — warp-autonomous register-streaming stencil
// inputs: input_img, output_img, roi_mask  [32,1,512,512] f32
// output: [intensity, texture, shape, total] (4 x f32)
//
// 2048 warps; each warp: one 256-col half x 16-row chunk of one image.
// 8 cols/lane in registers, 3-row window reloaded (L1-resident), shuffles for
// column neighbors, zero smem / zero barriers in the main loop.
// ---------------------------------------------------------------------------

#define HH 512
#define WW 512
#define BB 32
#define NBLK 256
#define NTHR 256
#define FULLM 0xffffffffu

__device__ double g_part[NBLK][11];

__device__ __forceinline__ float4 ld4z(const float* __restrict__ p, bool ok) {
    return ok ? *(const float4*)p : make_float4(0.f, 0.f, 0.f, 0.f);
}

// Compute 3x3 local variance, laplacian, and center value for 8 columns.
__device__ __forceinline__ void stencil8(
    const float* __restrict__ base, int r, int cb,
    bool okm, bool okp, bool hasL, bool hasR, int lane,
    float* __restrict__ var, float* __restrict__ lap, float* __restrict__ cen)
{
    const float* p = base + r * WW + cb;
    float a0[8], a1[8], a2[8];
    float4 q;
    q = ld4z(p - WW,     okm); a0[0]=q.x; a0[1]=q.y; a0[2]=q.z; a0[3]=q.w;
    q = ld4z(p - WW + 4, okm); a0[4]=q.x; a0[5]=q.y; a0[6]=q.z; a0[7]=q.w;
    q = *(const float4*)(p);     a1[0]=q.x; a1[1]=q.y; a1[2]=q.z; a1[3]=q.w;
    q = *(const float4*)(p + 4); a1[4]=q.x; a1[5]=q.y; a1[6]=q.z; a1[7]=q.w;
    q = ld4z(p + WW,     okp); a2[0]=q.x; a2[1]=q.y; a2[2]=q.z; a2[3]=q.w;
    q = ld4z(p + WW + 4, okp); a2[4]=q.x; a2[5]=q.y; a2[6]=q.z; a2[7]=q.w;

    // strip-edge halo columns (zero at true image boundary)
    float hl0=0.f, hl1=0.f, hl2=0.f, hr0=0.f, hr1=0.f, hr2=0.f;
    if (lane == 0 && hasL) {
        const float* pl = base + r * WW + cb - 1;
        hl1 = pl[0];
        if (okm) hl0 = pl[-WW];
        if (okp) hl2 = pl[ WW];
    }
    if (lane == 31 && hasR) {
        const float* pr = base + r * WW + cb + 8;
        hr1 = pr[0];
        if (okm) hr0 = pr[-WW];
        if (okp) hr2 = pr[ WW];
    }

    float cs[8], cq[8];
    #pragma unroll
    for (int j = 0; j < 8; j++) {
        cs[j] = a0[j] + a1[j] + a2[j];
        float u = a0[j] * a0[j];
        u = fmaf(a1[j], a1[j], u);
        cq[j] = fmaf(a2[j], a2[j], u);
    }

    float csL = __shfl_up_sync(FULLM, cs[7], 1);
    float cqL = __shfl_up_sync(FULLM, cq[7], 1);
    float aL  = __shfl_up_sync(FULLM, a1[7], 1);
    if (lane == 0) {
        csL = hl0 + hl1 + hl2;
        float u = hl0 * hl0; u = fmaf(hl1, hl1, u);
        cqL = fmaf(hl2, hl2, u);
        aL  = hl1;
    }
    float csR = __shfl_down_sync(FULLM, cs[0], 1);
    float cqR = __shfl_down_sync(FULLM, cq[0], 1);
    float aR  = __shfl_down_sync(FULLM, a1[0], 1);
    if (lane == 31) {
        csR = hr0 + hr1 + hr2;
        float u = hr0 * hr0; u = fmaf(hr1, hr1, u);
        cqR = fmaf(hr2, hr2, u);
        aR  = hr1;
    }

    const float inv9 = 1.f / 9.f;
    #pragma unroll
    for (int j = 0; j < 8; j++) {
        float cm = (j == 0) ? csL : cs[j - 1];
        float cp = (j == 7) ? csR : cs[j + 1];
        float qm = (j == 0) ? cqL : cq[j - 1];
        float qp = (j == 7) ? cqR : cq[j + 1];
        float S = cm + cs[j] + cp;
        float Q = qm + cq[j] + qp;
        float bmn = S * inv9;
        var[j] = fmaf(-bmn, bmn, Q * inv9);
        float am = (j == 0) ? aL : a1[j - 1];
        float ap = (j == 7) ? aR : a1[j + 1];
        lap[j] = fmaf(-5.f, a1[j], cs[j] + am + ap);
        cen[j] = a1[j];
    }
}

__global__ void __launch_bounds__(NTHR) k_main(
    const float* __restrict__ g_in,
    const float* __restrict__ g_out,
    const float* __restrict__ g_mask)
{
    __shared__ float sred[11][8];

    const int t    = threadIdx.x;
    const int lane = t & 31;
    const int wid  = t >> 5;
    const int gw   = blockIdx.x * 8 + wid;   // 0..2047

    const int img   = gw >> 6;               // 64 warps per image
    const int chunk = (gw >> 1) & 31;        // 16-row chunk
    const int half  = gw & 1;                // 256-col half
    const int c0    = half << 8;
    const int cb    = c0 + lane * 8;
    const bool hasL = (c0 > 0);
    const bool hasR = (c0 + 256 < WW);

    const float* bi = g_in   + (size_t)img * HH * WW;
    const float* bo = g_out  + (size_t)img * HH * WW;
    const float* bm = g_mask + (size_t)img * HH * WW;

    float msum = 0.f;
    float xi1 = 0.f, xi2 = 0.f, xi3 = 0.f, xi4 = 0.f;
    float yo1 = 0.f, yo2 = 0.f, yo3 = 0.f, yo4 = 0.f;
    float texs = 0.f, shps = 0.f;

    const int r0 = chunk * 16;
    for (int r = r0; r < r0 + 16; r++) {
        const bool okm = (r > 0);
        const bool okp = (r < HH - 1);

        float var_i[8], lap_i[8], xc[8];
        stencil8(bi, r, cb, okm, okp, hasL, hasR, lane, var_i, lap_i, xc);
        float var_o[8], lap_o[8], yc[8];
        stencil8(bo, r, cb, okm, okp, hasL, hasR, lane, var_o, lap_o, yc);

        const float* pm = bm + r * WW + cb;
        float4 m0 = *(const float4*)(pm);
        float4 m1 = *(const float4*)(pm + 4);
        float mv[8] = { m0.x, m0.y, m0.z, m0.w, m1.x, m1.y, m1.z, m1.w };

        #pragma unroll
        for (int j = 0; j < 8; j++) {
            float m = mv[j];
            msum += m;
            float x = xc[j], y = yc[j];
            float x2 = x * x, y2 = y * y;
            float qx = x2 * m, qy = y2 * m;
            xi1 = fmaf(x, m, xi1);  xi2 += qx;
            xi3 = fmaf(x, qx, xi3); xi4 = fmaf(x2, qx, xi4);
            yo1 = fmaf(y, m, yo1);  yo2 += qy;
            yo3 = fmaf(y, qy, yo3); yo4 = fmaf(y2, qy, yo4);
            texs = fmaf(fabsf(var_o[j] - var_i[j]), m, texs);
            shps = fmaf(fabsf(lap_o[j] - lap_i[j]), m, shps);
        }
    }

    // block reduction: warp shuffle -> smem -> fp64 partial per block
    float acc[11] = { msum, xi1, xi2, xi3, xi4, yo1, yo2, yo3, yo4, texs, shps };
    #pragma unroll
    for (int k = 0; k < 11; k++) {
        float v = acc[k];
        #pragma unroll
        for (int off = 16; off; off >>= 1)
            v += __shfl_xor_sync(FULLM, v, off);
        if (lane == 0) sred[k][wid] = v;
    }
    __syncthreads();
    if (t < 11) {
        double s = 0.0;
        #pragma unroll
        for (int w = 0; w < 8; w++) s += (double)sred[t][w];
        g_part[blockIdx.x][t] = s;
    }
}

__global__ void k_final(float* __restrict__ out) {
    __shared__ double sacc[11];
    const int t = threadIdx.x, w = t >> 5, l = t & 31;

    if (w < 11) {
        double s = 0.0;
        #pragma unroll
        for (int b = 0; b < NBLK / 32; b++)
            s += g_part[l + b * 32][w];
        #pragma unroll
        for (int off = 16; off; off >>= 1)
            s += __shfl_xor_sync(FULLM, s, off);
        if (l == 0) sacc[w] = s;
    }
    __syncthreads();
    if (t == 0) {
        const double EPS = 1e-8;
        const double NTOT = (double)BB * HH * WW;

        double M0 = sacc[0];
        double ms = M0 + EPS;
        double Mi1 = sacc[1], Mi2 = sacc[2], Mi3 = sacc[3], Mi4 = sacc[4];
        double Mo1 = sacc[5], Mo2 = sacc[6], Mo3 = sacc[7], Mo4 = sacc[8];

        double im = Mi1 / ms, om = Mo1 / ms;
        double im2 = im * im, om2 = om * om;

        double c2i = Mi2 - 2.0 * im * Mi1 + im2 * M0;
        double c3i = Mi3 - 3.0 * im * Mi2 + 3.0 * im2 * Mi1 - im2 * im * M0;
        double c4i = Mi4 - 4.0 * im * Mi3 + 6.0 * im2 * Mi2 - 4.0 * im2 * im * Mi1 + im2 * im2 * M0;

        double c2o = Mo2 - 2.0 * om * Mo1 + om2 * M0;
        double c3o = Mo3 - 3.0 * om * Mo2 + 3.0 * om2 * Mo1 - om2 * om * M0;
        double c4o = Mo4 - 4.0 * om * Mo3 + 6.0 * om2 * Mo2 - 4.0 * om2 * om * Mo1 + om2 * om2 * M0;

        double iv = c2i / ms, ov = c2o / ms;
        double isk = c3i / (ms * (iv * sqrt(iv) + EPS));
        double osk = c3o / (ms * (ov * sqrt(ov) + EPS));
        double iku = c4i / (ms * (iv * iv + EPS));
        double oku = c4o / (ms * (ov * ov + EPS));

        double dm = im - om, dv = iv - ov, dsk = isk - osk, dku = iku - oku;
        double inten = dm * dm + dv * dv + dsk * dsk + dku * dku;
        double tex = sacc[9]  / NTOT;
        double shp = sacc[10] / NTOT;
        double total = inten + tex + 0.5 * shp;

        out[0] = (float)inten;
        out[1] = (float)tex;
        out[2] = (float)shp;
        out[3] = (float)total;
    }
}

extern "C" void kernel_launch(void* const* d_in, const int* in_sizes, int n_in,
                              void* d_out, int out_size) {
    const float* in_img  = (const float*)d_in[0];
    const float* out_img = (const float*)d_in[1];
    const float* mask    = (const float*)d_in[2];

    k_main<<<NBLK, NTHR>>>(in_img, out_img, mask);
    k_final<<<1, 352>>>((float*)d_out);
}

// round 3
// speedup vs baseline: 1.7420x; 1.1122x over previous
#include <cuda_runtime.h>
#include <math.h>

// ---------------------------------------------------------------------------
// RadiomicsPreservationLoss — warp-autonomous register-streaming stencil,
// single fused kernel (last-block finalize), balanced 296-block grid.
// inputs: input_img, output_img, roi_mask  [32,1,512,512] f32
// output: [intensity, texture, shape, total] (4 x f32)
// ---------------------------------------------------------------------------

#define HH 512
#define WW 512
#define BB 32
#define NBLK 296                    // exactly 2 blocks per SM at occ 2
#define NTHR 256
#define NSLOTS (NBLK * 8)           // 2368 warp slots
#define NCHUNK 4096                 // 32 img * 64 row-chunks(8 rows) * 2 halves
#define FULLM 0xffffffffu

__device__ double g_part[NBLK][11];
__device__ unsigned g_cnt = 0;

__device__ __forceinline__ float4 ld4z(const float* __restrict__ p, bool ok) {
    return ok ? *(const float4*)p : make_float4(0.f, 0.f, 0.f, 0.f);
}

// 3x3 local variance, laplacian, center value for 8 columns per lane.
__device__ __forceinline__ void stencil8(
    const float* __restrict__ base, int r, int cb,
    bool okm, bool okp, bool hasL, bool hasR, int lane,
    float* __restrict__ var, float* __restrict__ lap, float* __restrict__ cen)
{
    const float* p = base + r * WW + cb;
    float a0[8], a1[8], a2[8];
    float4 q;
    q = ld4z(p - WW,     okm); a0[0]=q.x; a0[1]=q.y; a0[2]=q.z; a0[3]=q.w;
    q = ld4z(p - WW + 4, okm); a0[4]=q.x; a0[5]=q.y; a0[6]=q.z; a0[7]=q.w;
    q = *(const float4*)(p);     a1[0]=q.x; a1[1]=q.y; a1[2]=q.z; a1[3]=q.w;
    q = *(const float4*)(p + 4); a1[4]=q.x; a1[5]=q.y; a1[6]=q.z; a1[7]=q.w;
    q = ld4z(p + WW,     okp); a2[0]=q.x; a2[1]=q.y; a2[2]=q.z; a2[3]=q.w;
    q = ld4z(p + WW + 4, okp); a2[4]=q.x; a2[5]=q.y; a2[6]=q.z; a2[7]=q.w;

    float hl0=0.f, hl1=0.f, hl2=0.f, hr0=0.f, hr1=0.f, hr2=0.f;
    if (lane == 0 && hasL) {
        const float* pl = base + r * WW + cb - 1;
        hl1 = pl[0];
        if (okm) hl0 = pl[-WW];
        if (okp) hl2 = pl[ WW];
    }
    if (lane == 31 && hasR) {
        const float* pr = base + r * WW + cb + 8;
        hr1 = pr[0];
        if (okm) hr0 = pr[-WW];
        if (okp) hr2 = pr[ WW];
    }

    float cs[8], cq[8];
    #pragma unroll
    for (int j = 0; j < 8; j++) {
        cs[j] = a0[j] + a1[j] + a2[j];
        float u = a0[j] * a0[j];
        u = fmaf(a1[j], a1[j], u);
        cq[j] = fmaf(a2[j], a2[j], u);
    }

    float csL = __shfl_up_sync(FULLM, cs[7], 1);
    float cqL = __shfl_up_sync(FULLM, cq[7], 1);
    float aL  = __shfl_up_sync(FULLM, a1[7], 1);
    if (lane == 0) {
        csL = hl0 + hl1 + hl2;
        float u = hl0 * hl0; u = fmaf(hl1, hl1, u);
        cqL = fmaf(hl2, hl2, u);
        aL  = hl1;
    }
    float csR = __shfl_down_sync(FULLM, cs[0], 1);
    float cqR = __shfl_down_sync(FULLM, cq[0], 1);
    float aR  = __shfl_down_sync(FULLM, a1[0], 1);
    if (lane == 31) {
        csR = hr0 + hr1 + hr2;
        float u = hr0 * hr0; u = fmaf(hr1, hr1, u);
        cqR = fmaf(hr2, hr2, u);
        aR  = hr1;
    }

    const float inv9 = 1.f / 9.f;
    #pragma unroll
    for (int j = 0; j < 8; j++) {
        float cm = (j == 0) ? csL : cs[j - 1];
        float cp = (j == 7) ? csR : cs[j + 1];
        float qm = (j == 0) ? cqL : cq[j - 1];
        float qp = (j == 7) ? cqR : cq[j + 1];
        float S = cm + cs[j] + cp;
        float Q = qm + cq[j] + qp;
        float bmn = S * inv9;
        var[j] = fmaf(-bmn, bmn, Q * inv9);
        float am = (j == 0) ? aL : a1[j - 1];
        float ap = (j == 7) ? aR : a1[j + 1];
        lap[j] = fmaf(-5.f, a1[j], cs[j] + am + ap);
        cen[j] = a1[j];
    }
}

__global__ void __launch_bounds__(NTHR, 2) k_main(
    const float* __restrict__ g_in,
    const float* __restrict__ g_out,
    const float* __restrict__ g_mask,
    float* __restrict__ final_out)
{
    __shared__ float sred[11][8];
    __shared__ bool s_last;
    __shared__ double sacc[11];

    const int t    = threadIdx.x;
    const int lane = t & 31;
    const int wid  = t >> 5;
    const int slot = blockIdx.x * 8 + wid;   // 0..2367

    float msum = 0.f;
    float xi1 = 0.f, xi2 = 0.f, xi3 = 0.f, xi4 = 0.f;
    float yo1 = 0.f, yo2 = 0.f, yo3 = 0.f, yo4 = 0.f;
    float texs = 0.f, shps = 0.f;

    for (int c = slot; c < NCHUNK; c += NSLOTS) {
        const int img   = c >> 7;            // 128 chunks per image
        const int rc    = (c >> 1) & 63;     // 8-row chunk
        const int half  = c & 1;
        const int c0    = half << 8;
        const int cb    = c0 + lane * 8;
        const bool hasL = (c0 > 0);
        const bool hasR = (c0 + 256 < WW);

        const float* bi = g_in   + (size_t)img * HH * WW;
        const float* bo = g_out  + (size_t)img * HH * WW;
        const float* bm = g_mask + (size_t)img * HH * WW;

        const int r0 = rc * 8;
        for (int r = r0; r < r0 + 8; r++) {
            const bool okm = (r > 0);
            const bool okp = (r < HH - 1);

            float var_i[8], lap_i[8], xc[8];
            stencil8(bi, r, cb, okm, okp, hasL, hasR, lane, var_i, lap_i, xc);
            float var_o[8], lap_o[8], yc[8];
            stencil8(bo, r, cb, okm, okp, hasL, hasR, lane, var_o, lap_o, yc);

            const float* pm = bm + r * WW + cb;
            float4 m0 = *(const float4*)(pm);
            float4 m1 = *(const float4*)(pm + 4);
            float mv[8] = { m0.x, m0.y, m0.z, m0.w, m1.x, m1.y, m1.z, m1.w };

            #pragma unroll
            for (int j = 0; j < 8; j++) {
                float m = mv[j];
                msum += m;
                float x = xc[j], y = yc[j];
                float x2 = x * x, y2 = y * y;
                float qx = x2 * m, qy = y2 * m;
                xi1 = fmaf(x, m, xi1);  xi2 += qx;
                xi3 = fmaf(x, qx, xi3); xi4 = fmaf(x2, qx, xi4);
                yo1 = fmaf(y, m, yo1);  yo2 += qy;
                yo3 = fmaf(y, qy, yo3); yo4 = fmaf(y2, qy, yo4);
                texs = fmaf(fabsf(var_o[j] - var_i[j]), m, texs);
                shps = fmaf(fabsf(lap_o[j] - lap_i[j]), m, shps);
            }
        }
    }

    // ---- block reduction -> fp64 partial ----
    float acc[11] = { msum, xi1, xi2, xi3, xi4, yo1, yo2, yo3, yo4, texs, shps };
    #pragma unroll
    for (int k = 0; k < 11; k++) {
        float v = acc[k];
        #pragma unroll
        for (int off = 16; off; off >>= 1)
            v += __shfl_xor_sync(FULLM, v, off);
        if (lane == 0) sred[k][wid] = v;
    }
    __syncthreads();
    if (t < 11) {
        double s = 0.0;
        #pragma unroll
        for (int w = 0; w < 8; w++) s += (double)sred[t][w];
        g_part[blockIdx.x][t] = s;
    }

    // ---- last-block finalize ----
    __threadfence();
    if (t == 0) {
        unsigned prev = atomicAdd(&g_cnt, 1u);
        s_last = (prev == NBLK - 1);
    }
    __syncthreads();
    if (!s_last) return;

    // accumulators 0..7 on warps 0..7, 8..10 on warps 0..2 (second pass)
    for (int k = wid; k < 11; k += 8) {
        double s = 0.0;
        for (int b = lane; b < NBLK; b += 32)
            s += g_part[b][k];
        #pragma unroll
        for (int off = 16; off; off >>= 1)
            s += __shfl_xor_sync(FULLM, s, off);
        if (lane == 0) sacc[k] = s;
    }
    __syncthreads();

    if (t == 0) {
        g_cnt = 0;   // reset for next graph replay
        const double EPS = 1e-8;
        const double NTOT = (double)BB * HH * WW;

        double M0 = sacc[0];
        double ms = M0 + EPS;
        double Mi1 = sacc[1], Mi2 = sacc[2], Mi3 = sacc[3], Mi4 = sacc[4];
        double Mo1 = sacc[5], Mo2 = sacc[6], Mo3 = sacc[7], Mo4 = sacc[8];

        double im = Mi1 / ms, om = Mo1 / ms;
        double im2 = im * im, om2 = om * om;

        double c2i = Mi2 - 2.0 * im * Mi1 + im2 * M0;
        double c3i = Mi3 - 3.0 * im * Mi2 + 3.0 * im2 * Mi1 - im2 * im * M0;
        double c4i = Mi4 - 4.0 * im * Mi3 + 6.0 * im2 * Mi2 - 4.0 * im2 * im * Mi1 + im2 * im2 * M0;

        double c2o = Mo2 - 2.0 * om * Mo1 + om2 * M0;
        double c3o = Mo3 - 3.0 * om * Mo2 + 3.0 * om2 * Mo1 - om2 * om * M0;
        double c4o = Mo4 - 4.0 * om * Mo3 + 6.0 * om2 * Mo2 - 4.0 * om2 * om * Mo1 + om2 * om2 * M0;

        double iv = c2i / ms, ov = c2o / ms;
        double isk = c3i / (ms * (iv * sqrt(iv) + EPS));
        double osk = c3o / (ms * (ov * sqrt(ov) + EPS));
        double iku = c4i / (ms * (iv * iv + EPS));
        double oku = c4o / (ms * (ov * ov + EPS));

        double dm = im - om, dv = iv - ov, dsk = isk - osk, dku = iku - oku;
        double inten = dm * dm + dv * dv + dsk * dsk + dku * dku;
        double tex = sacc[9]  / NTOT;
        double shp = sacc[10] / NTOT;
        double total = inten + tex + 0.5 * shp;

        final_out[0] = (float)inten;
        final_out[1] = (float)tex;
        final_out[2] = (float)shp;
        final_out[3] = (float)total;
    }
}

extern "C" void kernel_launch(void* const* d_in, const int* in_sizes, int n_in,
                              void* d_out, int out_size) {
    const float* in_img  = (const float*)d_in[0];
    const float* out_img = (const float*)d_in[1];
    const float* mask    = (const float*)d_in[2];

    k_main<<<NBLK, NTHR>>>(in_img, out_img, mask, (float*)d_out);
}

// round 4
// speedup vs baseline: 1.9128x; 1.0980x over previous
#include <cuda_runtime.h>
#include <math.h>

// ---------------------------------------------------------------------------
// RadiomicsPreservationLoss — warp-autonomous register-streaming stencil.
// Round 4: 4 cols/lane (float4), occ-3 (__launch_bounds__(256,3)), 444 blocks,
// 4-row x 128-col chunks grid-strided, fused last-block finalize.
// inputs: input_img, output_img, roi_mask  [32,1,512,512] f32
// output: [intensity, texture, shape, total] (4 x f32)
// ---------------------------------------------------------------------------

#define HH 512
#define WW 512
#define BB 32
#define NBLK 444                    // 3 blocks per SM on 148 SMs
#define NTHR 256
#define NSLOTS (NBLK * 8)           // 3552 warp slots
#define NCHUNK 16384                // 32 img * 128 row-chunks(4) * 4 strips
#define FULLM 0xffffffffu

__device__ double g_part[NBLK][11];
__device__ unsigned g_cnt = 0;

__device__ __forceinline__ float4 ld4z(const float* __restrict__ p, bool ok) {
    return ok ? *(const float4*)p : make_float4(0.f, 0.f, 0.f, 0.f);
}

// 3x3 local variance, laplacian, center value for 4 columns per lane.
__device__ __forceinline__ void stencil4(
    const float* __restrict__ base, int r, int cb,
    bool okm, bool okp, bool hasL, bool hasR, int lane,
    float* __restrict__ var, float* __restrict__ lap, float* __restrict__ cen)
{
    const float* p = base + r * WW + cb;
    float a0[4], a1[4], a2[4];
    float4 q;
    q = ld4z(p - WW, okm);   a0[0]=q.x; a0[1]=q.y; a0[2]=q.z; a0[3]=q.w;
    q = *(const float4*)(p); a1[0]=q.x; a1[1]=q.y; a1[2]=q.z; a1[3]=q.w;
    q = ld4z(p + WW, okp);   a2[0]=q.x; a2[1]=q.y; a2[2]=q.z; a2[3]=q.w;

    // strip-edge halo columns (zero at true image boundary)
    float hl0=0.f, hl1=0.f, hl2=0.f, hr0=0.f, hr1=0.f, hr2=0.f;
    if (lane == 0 && hasL) {
        const float* pl = p - 1;
        hl1 = pl[0];
        if (okm) hl0 = pl[-WW];
        if (okp) hl2 = pl[ WW];
    }
    if (lane == 31 && hasR) {
        const float* pr = p + 4;
        hr1 = pr[0];
        if (okm) hr0 = pr[-WW];
        if (okp) hr2 = pr[ WW];
    }

    float cs[4], cq[4];
    #pragma unroll
    for (int j = 0; j < 4; j++) {
        cs[j] = a0[j] + a1[j] + a2[j];
        float u = a0[j] * a0[j];
        u = fmaf(a1[j], a1[j], u);
        cq[j] = fmaf(a2[j], a2[j], u);
    }

    float csL = __shfl_up_sync(FULLM, cs[3], 1);
    float cqL = __shfl_up_sync(FULLM, cq[3], 1);
    float aL  = __shfl_up_sync(FULLM, a1[3], 1);
    if (lane == 0) {
        csL = hl0 + hl1 + hl2;
        float u = hl0 * hl0; u = fmaf(hl1, hl1, u);
        cqL = fmaf(hl2, hl2, u);
        aL  = hl1;
    }
    float csR = __shfl_down_sync(FULLM, cs[0], 1);
    float cqR = __shfl_down_sync(FULLM, cq[0], 1);
    float aR  = __shfl_down_sync(FULLM, a1[0], 1);
    if (lane == 31) {
        csR = hr0 + hr1 + hr2;
        float u = hr0 * hr0; u = fmaf(hr1, hr1, u);
        cqR = fmaf(hr2, hr2, u);
        aR  = hr1;
    }

    const float inv9 = 1.f / 9.f;
    #pragma unroll
    for (int j = 0; j < 4; j++) {
        float cm = (j == 0) ? csL : cs[j - 1];
        float cp = (j == 3) ? csR : cs[j + 1];
        float qm = (j == 0) ? cqL : cq[j - 1];
        float qp = (j == 3) ? cqR : cq[j + 1];
        float S = cm + cs[j] + cp;
        float Q = qm + cq[j] + qp;
        float bmn = S * inv9;
        var[j] = fmaf(-bmn, bmn, Q * inv9);
        float am = (j == 0) ? aL : a1[j - 1];
        float ap = (j == 3) ? aR : a1[j + 1];
        lap[j] = fmaf(-5.f, a1[j], cs[j] + am + ap);
        cen[j] = a1[j];
    }
}

__global__ void __launch_bounds__(NTHR, 3) k_main(
    const float* __restrict__ g_in,
    const float* __restrict__ g_out,
    const float* __restrict__ g_mask,
    float* __restrict__ final_out)
{
    __shared__ float sred[11][8];
    __shared__ bool s_last;
    __shared__ double sacc[11];

    const int t    = threadIdx.x;
    const int lane = t & 31;
    const int wid  = t >> 5;
    const int slot = blockIdx.x * 8 + wid;   // 0..3551

    float msum = 0.f;
    float xi1 = 0.f, xi2 = 0.f, xi3 = 0.f, xi4 = 0.f;
    float yo1 = 0.f, yo2 = 0.f, yo3 = 0.f, yo4 = 0.f;
    float texs = 0.f, shps = 0.f;

    for (int c = slot; c < NCHUNK; c += NSLOTS) {
        const int img   = c >> 9;            // 512 chunks per image
        const int rc    = (c >> 2) & 127;    // 4-row chunk
        const int strip = c & 3;             // 128-col strip
        const int c0    = strip << 7;
        const int cb    = c0 + lane * 4;
        const bool hasL = (strip > 0);
        const bool hasR = (strip < 3);

        const float* bi = g_in   + (size_t)img * HH * WW;
        const float* bo = g_out  + (size_t)img * HH * WW;
        const float* bm = g_mask + (size_t)img * HH * WW;

        const int r0 = rc * 4;
        #pragma unroll
        for (int dr = 0; dr < 4; dr++) {
            const int r = r0 + dr;
            const bool okm = (r > 0);
            const bool okp = (r < HH - 1);

            float var_i[4], lap_i[4], xc[4];
            stencil4(bi, r, cb, okm, okp, hasL, hasR, lane, var_i, lap_i, xc);
            float var_o[4], lap_o[4], yc[4];
            stencil4(bo, r, cb, okm, okp, hasL, hasR, lane, var_o, lap_o, yc);

            float4 m0 = *(const float4*)(bm + r * WW + cb);
            float mv[4] = { m0.x, m0.y, m0.z, m0.w };

            #pragma unroll
            for (int j = 0; j < 4; j++) {
                float m = mv[j];
                msum += m;
                float x = xc[j], y = yc[j];
                float x2 = x * x, y2 = y * y;
                float qx = x2 * m, qy = y2 * m;
                xi1 = fmaf(x, m, xi1);  xi2 += qx;
                xi3 = fmaf(x, qx, xi3); xi4 = fmaf(x2, qx, xi4);
                yo1 = fmaf(y, m, yo1);  yo2 += qy;
                yo3 = fmaf(y, qy, yo3); yo4 = fmaf(y2, qy, yo4);
                texs = fmaf(fabsf(var_o[j] - var_i[j]), m, texs);
                shps = fmaf(fabsf(lap_o[j] - lap_i[j]), m, shps);
            }
        }
    }

    // ---- block reduction -> fp64 partial ----
    float acc[11] = { msum, xi1, xi2, xi3, xi4, yo1, yo2, yo3, yo4, texs, shps };
    #pragma unroll
    for (int k = 0; k < 11; k++) {
        float v = acc[k];
        #pragma unroll
        for (int off = 16; off; off >>= 1)
            v += __shfl_xor_sync(FULLM, v, off);
        if (lane == 0) sred[k][wid] = v;
    }
    __syncthreads();
    if (t < 11) {
        double s = 0.0;
        #pragma unroll
        for (int w = 0; w < 8; w++) s += (double)sred[t][w];
        g_part[blockIdx.x][t] = s;
    }

    // ---- last-block finalize ----
    __threadfence();
    if (t == 0) {
        unsigned prev = atomicAdd(&g_cnt, 1u);
        s_last = (prev == NBLK - 1);
    }
    __syncthreads();
    if (!s_last) return;

    for (int k = wid; k < 11; k += 8) {
        double s = 0.0;
        for (int b = lane; b < NBLK; b += 32)
            s += g_part[b][k];
        #pragma unroll
        for (int off = 16; off; off >>= 1)
            s += __shfl_xor_sync(FULLM, s, off);
        if (lane == 0) sacc[k] = s;
    }
    __syncthreads();

    if (t == 0) {
        g_cnt = 0;   // reset for next graph replay
        const double EPS = 1e-8;
        const double NTOT = (double)BB * HH * WW;

        double M0 = sacc[0];
        double ms = M0 + EPS;
        double Mi1 = sacc[1], Mi2 = sacc[2], Mi3 = sacc[3], Mi4 = sacc[4];
        double Mo1 = sacc[5], Mo2 = sacc[6], Mo3 = sacc[7], Mo4 = sacc[8];

        double im = Mi1 / ms, om = Mo1 / ms;
        double im2 = im * im, om2 = om * om;

        double c2i = Mi2 - 2.0 * im * Mi1 + im2 * M0;
        double c3i = Mi3 - 3.0 * im * Mi2 + 3.0 * im2 * Mi1 - im2 * im * M0;
        double c4i = Mi4 - 4.0 * im * Mi3 + 6.0 * im2 * Mi2 - 4.0 * im2 * im * Mi1 + im2 * im2 * M0;

        double c2o = Mo2 - 2.0 * om * Mo1 + om2 * M0;
        double c3o = Mo3 - 3.0 * om * Mo2 + 3.0 * om2 * Mo1 - om2 * om * M0;
        double c4o = Mo4 - 4.0 * om * Mo3 + 6.0 * om2 * Mo2 - 4.0 * om2 * om * Mo1 + om2 * om2 * M0;

        double iv = c2i / ms, ov = c2o / ms;
        double isk = c3i / (ms * (iv * sqrt(iv) + EPS));
        double osk = c3o / (ms * (ov * sqrt(ov) + EPS));
        double iku = c4i / (ms * (iv * iv + EPS));
        double oku = c4o / (ms * (ov * ov + EPS));

        double dm = im - om, dv = iv - ov, dsk = isk - osk, dku = iku - oku;
        double inten = dm * dm + dv * dv + dsk * dsk + dku * dku;
        double tex = sacc[9]  / NTOT;
        double shp = sacc[10] / NTOT;
        double total = inten + tex + 0.5 * shp;

        final_out[0] = (float)inten;
        final_out[1] = (float)tex;
        final_out[2] = (float)shp;
        final_out[3] = (float)total;
    }
}

extern "C" void kernel_launch(void* const* d_in, const int* in_sizes, int n_in,
                              void* d_out, int out_size) {
    const float* in_img  = (const float*)d_in[0];
    const float* out_img = (const float*)d_in[1];
    const float* mask    = (const float*)d_in[2];

    k_main<<<NBLK, NTHR>>>(in_img, out_img, mask, (float*)d_out);
}

// round 5
// speedup vs baseline: 1.9266x; 1.0072x over previous
#include <cuda_runtime.h>
#include <math.h>

// ---------------------------------------------------------------------------
// RadiomicsPreservationLoss — register-rolling stencil, branch-free halos.
// Round 5: 4-row rolling chunks (6 loads / 4 output rows per image),
// halo columns resolved once per loaded row (2 shfl + 2 predicated LDG),
// occ-3, 444 blocks, fused last-block finalize.
// ---------------------------------------------------------------------------

#define HH 512
#define WW 512
#define BB 32
#define NBLK 444                    // 3 blocks per SM on 148 SMs
#define NTHR 256
#define NSLOTS (NBLK * 8)           // 3552 warp slots
#define NCHUNK 16384                // 32 img * 128 row-chunks(4) * 4 strips
#define FULLM 0xffffffffu

__device__ double g_part[NBLK][11];
__device__ unsigned g_cnt = 0;

// Load one row as 6 values: 4 own cols (cb..cb+3) + left halo (cb-1) + right
// halo (cb+4). Branch-free: shuffles for interior lane edges, predicated LDG
// for strip edges, zeros outside the image.
__device__ __forceinline__ void load_row6(
    float* __restrict__ R, const float* __restrict__ base,
    int r, int cb, bool hasL, bool hasR, int lane)
{
    const bool ok = ((unsigned)r < (unsigned)HH);
    float4 q = make_float4(0.f, 0.f, 0.f, 0.f);
    if (ok) q = *(const float4*)(base + r * WW + cb);
    R[0] = q.x; R[1] = q.y; R[2] = q.z; R[3] = q.w;

    float al = __shfl_up_sync(FULLM, q.w, 1);     // lane-1's col cb+3 == my cb-1
    float ar = __shfl_down_sync(FULLM, q.x, 1);   // lane+1's col cb   == my cb+4
    float al_e = (lane == 0  && ok && hasL) ? base[r * WW + cb - 1] : 0.f;
    float ar_e = (lane == 31 && ok && hasR) ? base[r * WW + cb + 4] : 0.f;
    R[4] = (lane == 0)  ? al_e : al;
    R[5] = (lane == 31) ? ar_e : ar;
}

// 3x3 variance, laplacian, center for 4 cols from three rolled 6-wide rows.
__device__ __forceinline__ void proc6(
    const float* __restrict__ Ap, const float* __restrict__ Ac,
    const float* __restrict__ An,
    float* __restrict__ var, float* __restrict__ lap, float* __restrict__ cen)
{
    float cs[6], cq[6];
    #pragma unroll
    for (int j = 0; j < 6; j++) {
        cs[j] = Ap[j] + Ac[j] + An[j];
        float u = Ap[j] * Ap[j];
        u = fmaf(Ac[j], Ac[j], u);
        cq[j] = fmaf(An[j], An[j], u);
    }
    const float inv9 = 1.f / 9.f;
    #pragma unroll
    for (int p = 0; p < 4; p++) {
        float Sm = (p == 0) ? cs[4] : cs[p - 1];
        float Sp = (p == 3) ? cs[5] : cs[p + 1];
        float Qm = (p == 0) ? cq[4] : cq[p - 1];
        float Qp = (p == 3) ? cq[5] : cq[p + 1];
        float S = Sm + cs[p] + Sp;
        float Q = Qm + cq[p] + Qp;
        float bmn = S * inv9;
        var[p] = fmaf(-bmn, bmn, Q * inv9);
        float am = (p == 0) ? Ac[4] : Ac[p - 1];
        float ap = (p == 3) ? Ac[5] : Ac[p + 1];
        lap[p] = fmaf(-5.f, Ac[p], cs[p] + am + ap);
        cen[p] = Ac[p];
    }
}

__global__ void __launch_bounds__(NTHR, 3) k_main(
    const float* __restrict__ g_in,
    const float* __restrict__ g_out,
    const float* __restrict__ g_mask,
    float* __restrict__ final_out)
{
    __shared__ float sred[11][8];
    __shared__ bool s_last;
    __shared__ double sacc[11];

    const int t    = threadIdx.x;
    const int lane = t & 31;
    const int wid  = t >> 5;
    const int slot = blockIdx.x * 8 + wid;   // 0..3551

    float msum = 0.f;
    float xi1 = 0.f, xi2 = 0.f, xi3 = 0.f, xi4 = 0.f;
    float yo1 = 0.f, yo2 = 0.f, yo3 = 0.f, yo4 = 0.f;
    float texs = 0.f, shps = 0.f;

    for (int c = slot; c < NCHUNK; c += NSLOTS) {
        const int img   = c >> 9;            // 512 chunks per image
        const int rc    = (c >> 2) & 127;    // 4-row chunk
        const int strip = c & 3;             // 128-col strip
        const int c0    = strip << 7;
        const int cb    = c0 + lane * 4;
        const bool hasL = (strip > 0);
        const bool hasR = (strip < 3);

        const float* bi = g_in   + (size_t)img * HH * WW;
        const float* bo = g_out  + (size_t)img * HH * WW;
        const float* bm = g_mask + (size_t)img * HH * WW;

        const int r0 = rc * 4;

        float Ai[3][6], Ao[3][6];
        load_row6(Ai[0], bi, r0 - 1, cb, hasL, hasR, lane);
        load_row6(Ao[0], bo, r0 - 1, cb, hasL, hasR, lane);
        load_row6(Ai[1], bi, r0,     cb, hasL, hasR, lane);
        load_row6(Ao[1], bo, r0,     cb, hasL, hasR, lane);

        #pragma unroll
        for (int dr = 0; dr < 4; dr++) {
            const int sp = dr % 3, sc = (dr + 1) % 3, sn = (dr + 2) % 3;
            load_row6(Ai[sn], bi, r0 + dr + 1, cb, hasL, hasR, lane);
            load_row6(Ao[sn], bo, r0 + dr + 1, cb, hasL, hasR, lane);

            float vi[4], li[4], xc[4];
            proc6(Ai[sp], Ai[sc], Ai[sn], vi, li, xc);
            float vo[4], lo[4], yc[4];
            proc6(Ao[sp], Ao[sc], Ao[sn], vo, lo, yc);

            float4 m0 = *(const float4*)(bm + (r0 + dr) * WW + cb);
            float mv[4] = { m0.x, m0.y, m0.z, m0.w };

            #pragma unroll
            for (int j = 0; j < 4; j++) {
                float m = mv[j];
                msum += m;
                float x = xc[j], y = yc[j];
                float x2 = x * x, y2 = y * y;
                float qx = x2 * m, qy = y2 * m;
                xi1 = fmaf(x, m, xi1);  xi2 += qx;
                xi3 = fmaf(x, qx, xi3); xi4 = fmaf(x2, qx, xi4);
                yo1 = fmaf(y, m, yo1);  yo2 += qy;
                yo3 = fmaf(y, qy, yo3); yo4 = fmaf(y2, qy, yo4);
                texs = fmaf(fabsf(vo[j] - vi[j]), m, texs);
                shps = fmaf(fabsf(lo[j] - li[j]), m, shps);
            }
        }
    }

    // ---- block reduction -> fp64 partial ----
    float acc[11] = { msum, xi1, xi2, xi3, xi4, yo1, yo2, yo3, yo4, texs, shps };
    #pragma unroll
    for (int k = 0; k < 11; k++) {
        float v = acc[k];
        #pragma unroll
        for (int off = 16; off; off >>= 1)
            v += __shfl_xor_sync(FULLM, v, off);
        if (lane == 0) sred[k][wid] = v;
    }
    __syncthreads();
    if (t < 11) {
        double s = 0.0;
        #pragma unroll
        for (int w = 0; w < 8; w++) s += (double)sred[t][w];
        g_part[blockIdx.x][t] = s;
    }

    // ---- last-block finalize ----
    __threadfence();
    if (t == 0) {
        unsigned prev = atomicAdd(&g_cnt, 1u);
        s_last = (prev == NBLK - 1);
    }
    __syncthreads();
    if (!s_last) return;

    for (int k = wid; k < 11; k += 8) {
        double s = 0.0;
        for (int b = lane; b < NBLK; b += 32)
            s += g_part[b][k];
        #pragma unroll
        for (int off = 16; off; off >>= 1)
            s += __shfl_xor_sync(FULLM, s, off);
        if (lane == 0) sacc[k] = s;
    }
    __syncthreads();

    if (t == 0) {
        g_cnt = 0;   // reset for next graph replay
        const double EPS = 1e-8;
        const double NTOT = (double)BB * HH * WW;

        double M0 = sacc[0];
        double ms = M0 + EPS;
        double Mi1 = sacc[1], Mi2 = sacc[2], Mi3 = sacc[3], Mi4 = sacc[4];
        double Mo1 = sacc[5], Mo2 = sacc[6], Mo3 = sacc[7], Mo4 = sacc[8];

        double im = Mi1 / ms, om = Mo1 / ms;
        double im2 = im * im, om2 = om * om;

        double c2i = Mi2 - 2.0 * im * Mi1 + im2 * M0;
        double c3i = Mi3 - 3.0 * im * Mi2 + 3.0 * im2 * Mi1 - im2 * im * M0;
        double c4i = Mi4 - 4.0 * im * Mi3 + 6.0 * im2 * Mi2 - 4.0 * im2 * im * Mi1 + im2 * im2 * M0;

        double c2o = Mo2 - 2.0 * om * Mo1 + om2 * M0;
        double c3o = Mo3 - 3.0 * om * Mo2 + 3.0 * om2 * Mo1 - om2 * om * M0;
        double c4o = Mo4 - 4.0 * om * Mo3 + 6.0 * om2 * Mo2 - 4.0 * om2 * om * Mo1 + om2 * om2 * M0;

        double iv = c2i / ms, ov = c2o / ms;
        double isk = c3i / (ms * (iv * sqrt(iv) + EPS));
        double osk = c3o / (ms * (ov * sqrt(ov) + EPS));
        double iku = c4i / (ms * (iv * iv + EPS));
        double oku = c4o / (ms * (ov * ov + EPS));

        double dm = im - om, dv = iv - ov, dsk = isk - osk, dku = iku - oku;
        double inten = dm * dm + dv * dv + dsk * dsk + dku * dku;
        double tex = sacc[9]  / NTOT;
        double shp = sacc[10] / NTOT;
        double total = inten + tex + 0.5 * shp;

        final_out[0] = (float)inten;
        final_out[1] = (float)tex;
        final_out[2] = (float)shp;
        final_out[3] = (float)total;
    }
}

extern "C" void kernel_launch(void* const* d_in, const int* in_sizes, int n_in,
                              void* d_out, int out_size) {
    const float* in_img  = (const float*)d_in[0];
    const float* out_img = (const float*)d_in[1];
    const float* mask    = (const float*)d_in[2];

    k_main<<<NBLK, NTHR>>>(in_img, out_img, mask, (float*)d_out);
}